// round 1
// baseline (speedup 1.0000x reference)
#include <cuda_runtime.h>
#include <cuda_bf16.h>
#include <math.h>

#define NG 131072
#define NM 40962
#define NE 524288
#define DD 128

#define TILE_R 64
#define TILE_K 16
#define NTHREADS 256

// scatter-sum accumulator for edge messages -> mesh nodes
__device__ float g_agg[(size_t)NM * DD];

__global__ void zero_agg_kernel() {
    size_t n = (size_t)NM * DD;
    for (size_t i = blockIdx.x * (size_t)blockDim.x + threadIdx.x; i < n;
         i += (size_t)gridDim.x * blockDim.x) {
        g_agg[i] = 0.0f;
    }
}

// MODE 0: edge MLP  (input = concat(efeat, grid[src], mesh[dst]), K1=384,
//                    epilogue = atomicAdd into g_agg[dst])
// MODE 1: plain MLP (input = Xa, K1=128, epilogue = resid + write out)
// MODE 2: dst MLP   (input = concat(g_agg, mesh), K1=256, epilogue = resid + write out)
template <int K1, int MODE>
__global__ __launch_bounds__(NTHREADS)
void mlp_kernel(const float* __restrict__ Xa,
                const float* __restrict__ Xb,
                const float* __restrict__ Xc,
                const int* __restrict__ src_idx,
                const int* __restrict__ dst_idx,
                const float* __restrict__ W0, const float* __restrict__ b0,
                const float* __restrict__ W1, const float* __restrict__ b1,
                const float* __restrict__ gamma, const float* __restrict__ beta,
                const float* __restrict__ resid,
                float* __restrict__ out,
                float* __restrict__ agg,
                int R)
{
    __shared__ float As[TILE_R][TILE_K + 1];   // [64][17] row-major
    __shared__ float Bs[TILE_K][DD + 4];       // [16][132]
    __shared__ float Hs[TILE_R][DD + 4];       // [64][132]

    const int t  = threadIdx.x;
    const int tx = t & 31;       // 32 col-groups of 4 cols
    const int ty = t >> 5;       // 8 row-groups of 8 rows (== warp id)
    const int rowBase = blockIdx.x * TILE_R;

    // ---------------- GEMM1: acc = X @ W0 ----------------
    float acc[8][4];
#pragma unroll
    for (int i = 0; i < 8; ++i)
#pragma unroll
        for (int j = 0; j < 4; ++j) acc[i][j] = 0.0f;

#pragma unroll 1
    for (int k0 = 0; k0 < K1; k0 += TILE_K) {
        // load A tile (64 x 16), gathered
        for (int i = t; i < TILE_R * TILE_K; i += NTHREADS) {
            int r  = i / TILE_K;
            int kk = i - r * TILE_K;
            int col = k0 + kk;
            int rg  = rowBase + r;
            float v = 0.0f;
            if (rg < R) {
                if (MODE == 0) {
                    if (col < 128)      v = Xa[(size_t)rg * 128 + col];
                    else if (col < 256) v = Xb[(size_t)src_idx[rg] * 128 + (col - 128)];
                    else                v = Xc[(size_t)dst_idx[rg] * 128 + (col - 256)];
                } else if (MODE == 1) {
                    v = Xa[(size_t)rg * 128 + col];
                } else { // MODE 2
                    if (col < 128) v = Xa[(size_t)rg * 128 + col];
                    else           v = Xb[(size_t)rg * 128 + (col - 128)];
                }
            }
            As[r][kk] = v;
        }
        // load B tile (16 x 128)
        for (int i = t; i < TILE_K * DD; i += NTHREADS) {
            int kr = i >> 7;
            int c  = i & 127;
            Bs[kr][c] = W0[(size_t)(k0 + kr) * DD + c];
        }
        __syncthreads();
#pragma unroll
        for (int k = 0; k < TILE_K; ++k) {
            float4 bv = *(const float4*)&Bs[k][tx * 4];
#pragma unroll
            for (int i = 0; i < 8; ++i) {
                float a = As[ty * 8 + i][k];
                acc[i][0] += a * bv.x;
                acc[i][1] += a * bv.y;
                acc[i][2] += a * bv.z;
                acc[i][3] += a * bv.w;
            }
        }
        __syncthreads();
    }

    // bias + SiLU -> Hs
    {
        float4 bb = *(const float4*)&b0[tx * 4];
#pragma unroll
        for (int i = 0; i < 8; ++i) {
            float x0 = acc[i][0] + bb.x;
            float x1 = acc[i][1] + bb.y;
            float x2 = acc[i][2] + bb.z;
            float x3 = acc[i][3] + bb.w;
            Hs[ty * 8 + i][tx * 4 + 0] = x0 / (1.0f + __expf(-x0));
            Hs[ty * 8 + i][tx * 4 + 1] = x1 / (1.0f + __expf(-x1));
            Hs[ty * 8 + i][tx * 4 + 2] = x2 / (1.0f + __expf(-x2));
            Hs[ty * 8 + i][tx * 4 + 3] = x3 / (1.0f + __expf(-x3));
        }
    }
    __syncthreads();

    // ---------------- GEMM2: y = H @ W1 ----------------
    float acc2[8][4];
#pragma unroll
    for (int i = 0; i < 8; ++i)
#pragma unroll
        for (int j = 0; j < 4; ++j) acc2[i][j] = 0.0f;

#pragma unroll 1
    for (int k0 = 0; k0 < DD; k0 += TILE_K) {
        for (int i = t; i < TILE_K * DD; i += NTHREADS) {
            int kr = i >> 7;
            int c  = i & 127;
            Bs[kr][c] = W1[(size_t)(k0 + kr) * DD + c];
        }
        __syncthreads();
#pragma unroll
        for (int k = 0; k < TILE_K; ++k) {
            float4 bv = *(const float4*)&Bs[k][tx * 4];
#pragma unroll
            for (int i = 0; i < 8; ++i) {
                float a = Hs[ty * 8 + i][k0 + k];
                acc2[i][0] += a * bv.x;
                acc2[i][1] += a * bv.y;
                acc2[i][2] += a * bv.z;
                acc2[i][3] += a * bv.w;
            }
        }
        __syncthreads();
    }

    // y = acc2 + b1 -> overwrite Hs (h fully consumed; each warp only touches its own rows)
    {
        float4 bb = *(const float4*)&b1[tx * 4];
#pragma unroll
        for (int i = 0; i < 8; ++i) {
            Hs[ty * 8 + i][tx * 4 + 0] = acc2[i][0] + bb.x;
            Hs[ty * 8 + i][tx * 4 + 1] = acc2[i][1] + bb.y;
            Hs[ty * 8 + i][tx * 4 + 2] = acc2[i][2] + bb.z;
            Hs[ty * 8 + i][tx * 4 + 3] = acc2[i][3] + bb.w;
        }
    }
    __syncthreads();

    // ---------------- LayerNorm + epilogue (warp w owns rows w*8..w*8+7) ----------------
    const int lane = tx;
    float4 gg = *(const float4*)&gamma[lane * 4];
    float4 bt = *(const float4*)&beta[lane * 4];

#pragma unroll 1
    for (int i = 0; i < 8; ++i) {
        int r  = ty * 8 + i;
        int rg = rowBase + r;
        float4 v = *(const float4*)&Hs[r][lane * 4];
        float s  = v.x + v.y + v.z + v.w;
        float ss = v.x * v.x + v.y * v.y + v.z * v.z + v.w * v.w;
#pragma unroll
        for (int off = 16; off > 0; off >>= 1) {
            s  += __shfl_xor_sync(0xFFFFFFFFu, s,  off);
            ss += __shfl_xor_sync(0xFFFFFFFFu, ss, off);
        }
        float mean = s * (1.0f / DD);
        float var  = ss * (1.0f / DD) - mean * mean;
        float rstd = rsqrtf(var + 1e-5f);

        float4 o;
        o.x = (v.x - mean) * rstd * gg.x + bt.x;
        o.y = (v.y - mean) * rstd * gg.y + bt.y;
        o.z = (v.z - mean) * rstd * gg.z + bt.z;
        o.w = (v.w - mean) * rstd * gg.w + bt.w;

        if (MODE == 0) {
            if (rg < R) {
                int di = dst_idx[rg];
                float* p = &agg[(size_t)di * DD + lane * 4];
                atomicAdd(p + 0, o.x);
                atomicAdd(p + 1, o.y);
                atomicAdd(p + 2, o.z);
                atomicAdd(p + 3, o.w);
            }
        } else {
            if (rg < R) {
                float4 rv = *(const float4*)&resid[(size_t)rg * DD + lane * 4];
                o.x += rv.x; o.y += rv.y; o.z += rv.z; o.w += rv.w;
                *(float4*)&out[(size_t)rg * DD + lane * 4] = o;
            }
        }
    }
}

extern "C" void kernel_launch(void* const* d_in, const int* in_sizes, int n_in,
                              void* d_out, int out_size)
{
    const float* efeat   = (const float*)d_in[0];
    const float* grid    = (const float*)d_in[1];
    const float* mesh    = (const float*)d_in[2];
    const int*   src_idx = (const int*)d_in[3];
    const int*   dst_idx = (const int*)d_in[4];
    const float* eW0 = (const float*)d_in[5];
    const float* eb0 = (const float*)d_in[6];
    const float* eW1 = (const float*)d_in[7];
    const float* eb1 = (const float*)d_in[8];
    const float* eg  = (const float*)d_in[9];
    const float* ebt = (const float*)d_in[10];
    const float* sW0 = (const float*)d_in[11];
    const float* sb0 = (const float*)d_in[12];
    const float* sW1 = (const float*)d_in[13];
    const float* sb1 = (const float*)d_in[14];
    const float* sg  = (const float*)d_in[15];
    const float* sbt = (const float*)d_in[16];
    const float* dW0 = (const float*)d_in[17];
    const float* db0 = (const float*)d_in[18];
    const float* dW1 = (const float*)d_in[19];
    const float* db1 = (const float*)d_in[20];
    const float* dg  = (const float*)d_in[21];
    const float* dbt = (const float*)d_in[22];

    float* out_grid = (float*)d_out;                       // [NG, 128]
    float* out_mesh = (float*)d_out + (size_t)NG * DD;     // [NM, 128]

    float* agg_ptr = nullptr;
    cudaGetSymbolAddress((void**)&agg_ptr, g_agg);

    // 1) zero the scatter accumulator
    zero_agg_kernel<<<1024, 256>>>();

    // 2) edge MLP + scatter-sum
    {
        int blocks = NE / TILE_R;  // 8192
        mlp_kernel<384, 0><<<blocks, NTHREADS>>>(
            efeat, grid, mesh, src_idx, dst_idx,
            eW0, eb0, eW1, eb1, eg, ebt,
            nullptr, nullptr, agg_ptr, NE);
    }

    // 3) src (grid) node MLP with residual
    {
        int blocks = NG / TILE_R;  // 2048
        mlp_kernel<128, 1><<<blocks, NTHREADS>>>(
            grid, nullptr, nullptr, nullptr, nullptr,
            sW0, sb0, sW1, sb1, sg, sbt,
            grid, out_grid, nullptr, NG);
    }

    // 4) dst (mesh) node MLP with residual (depends on edge scatter)
    {
        int blocks = (NM + TILE_R - 1) / TILE_R;  // 641
        mlp_kernel<256, 2><<<blocks, NTHREADS>>>(
            agg_ptr, mesh, nullptr, nullptr, nullptr,
            dW0, db0, dW1, db1, dg, dbt,
            mesh, out_mesh, nullptr, NM);
    }
}

// round 3
// speedup vs baseline: 1.9842x; 1.9842x over previous
#include <cuda_runtime.h>
#include <math.h>

#define NG 131072
#define NM 40962
#define NE 524288
#define DD 128

#define BLK_R 128
#define KC 16
#define NTH 256

#define AP 20    // As pitch (uint32 elems)  -> conflict-free frag reads
#define BP 136   // Bs pitch                 -> conflict-free frag reads
#define HP 132   // Hs pitch (float elems)

// smem byte offsets
#define OFF_AS 0         // 128*20*4  = 10240
#define OFF_BS 10240     // 16*136*4  = 8704
#define OFF_HS 18944     // 128*132*4 = 67584
#define OFF_IS 86528     // 128*4
#define OFF_ID 87040     // 128*4
#define SMEM_BYTES 87552

// scatter-sum accumulator for edge messages -> mesh nodes
__device__ float g_agg[(size_t)NM * DD];

__global__ void zero_agg_kernel() {
    size_t n = (size_t)NM * DD;
    for (size_t i = blockIdx.x * (size_t)blockDim.x + threadIdx.x; i < n;
         i += (size_t)gridDim.x * blockDim.x) {
        g_agg[i] = 0.0f;
    }
}

__device__ __forceinline__ unsigned f2tf32(float x) {
    unsigned u;
    asm("cvt.rna.tf32.f32 %0, %1;" : "=r"(u) : "f"(x));
    return u;
}

__device__ __forceinline__ void mma8(float* d, const unsigned* a, unsigned b0, unsigned b1) {
    asm volatile(
        "mma.sync.aligned.m16n8k8.row.col.f32.tf32.tf32.f32 "
        "{%0,%1,%2,%3}, {%4,%5,%6,%7}, {%8,%9}, {%0,%1,%2,%3};\n"
        : "+f"(d[0]), "+f"(d[1]), "+f"(d[2]), "+f"(d[3])
        : "r"(a[0]), "r"(a[1]), "r"(a[2]), "r"(a[3]), "r"(b0), "r"(b1));
}

// MODE 0: edge MLP  (input = concat(efeat, grid[src], mesh[dst]), K1=384,
//                    epilogue = red.v4 scatter into agg[dst])
// MODE 1: plain MLP (input = Xa, K1=128, epilogue = resid + write out)
// MODE 2: dst MLP   (input = concat(agg, mesh), K1=256, epilogue = resid + write out)
template <int K1, int MODE>
__global__ __launch_bounds__(NTH, 2)
void mlp_tc(const float* __restrict__ Xa,
            const float* __restrict__ Xb,
            const float* __restrict__ Xc,
            const int* __restrict__ src_idx,
            const int* __restrict__ dst_idx,
            const float* __restrict__ W0, const float* __restrict__ b0v,
            const float* __restrict__ W1, const float* __restrict__ b1v,
            const float* __restrict__ gamma, const float* __restrict__ beta,
            const float* __restrict__ resid,
            float* __restrict__ out,
            float* __restrict__ agg,
            int R)
{
    extern __shared__ unsigned char smem[];
    unsigned* As = (unsigned*)(smem + OFF_AS);
    unsigned* Bs = (unsigned*)(smem + OFF_BS);
    float*    Hs = (float*)(smem + OFF_HS);
    unsigned* Hu = (unsigned*)(smem + OFF_HS);
    int*      Is = (int*)(smem + OFF_IS);
    int*      Id = (int*)(smem + OFF_ID);

    const int t   = threadIdx.x;
    const int wid = t >> 5;
    const int l   = t & 31;
    const int lr  = l >> 2;   // fragment "group" row (0..7)
    const int lc  = l & 3;    // fragment col within quad (0..3)
    const int warpM = wid >> 1;          // 0..3
    const int warpN = wid & 1;           // 0..1
    const int wr0 = warpM * 32;
    const int wc0 = warpN * 64;
    const int rowBase = blockIdx.x * BLK_R;

    if (MODE == 0) {
        if (t < 128) {
            Is[t] = src_idx[rowBase + t];
            Id[t] = dst_idx[rowBase + t];
        }
    }
    __syncthreads();

    // ---------------- GEMM1: acc = tf32(X) @ tf32(W0) ----------------
    float acc[2][8][4];
#pragma unroll
    for (int m = 0; m < 2; ++m)
#pragma unroll
        for (int n = 0; n < 8; ++n)
#pragma unroll
            for (int j = 0; j < 4; ++j) acc[m][n][j] = 0.0f;

    const int kkA = t & 15;   // A-loader col within chunk
    const int rA  = t >> 4;   // A-loader row base (0..15)
    const int cB  = t & 127;  // B-loader col
    const int rB  = t >> 7;   // B-loader row base (0..1)

#pragma unroll 1
    for (int k0 = 0; k0 < K1; k0 += KC) {
        // load + convert A tile (128 x 16), gathered
#pragma unroll
        for (int j = 0; j < 8; ++j) {
            int r  = rA + j * 16;
            int rg = rowBase + r;
            int col = k0 + kkA;
            float v = 0.0f;
            if (rg < R) {
                if (MODE == 0) {
                    if (col < 128)      v = Xa[(size_t)rg * 128 + col];
                    else if (col < 256) v = Xb[(size_t)Is[r] * 128 + (col - 128)];
                    else                v = Xc[(size_t)Id[r] * 128 + (col - 256)];
                } else if (MODE == 1) {
                    v = Xa[(size_t)rg * 128 + col];
                } else {
                    if (col < 128) v = Xa[(size_t)rg * 128 + col];
                    else           v = Xb[(size_t)rg * 128 + (col - 128)];
                }
            }
            As[r * AP + kkA] = f2tf32(v);
        }
        // load + convert B tile (16 x 128)
#pragma unroll
        for (int j = 0; j < 8; ++j) {
            int row = rB + j * 2;
            Bs[row * BP + cB] = f2tf32(W0[(size_t)(k0 + row) * DD + cB]);
        }
        __syncthreads();

#pragma unroll
        for (int ks = 0; ks < 2; ++ks) {
            unsigned a[2][4];
#pragma unroll
            for (int mt = 0; mt < 2; ++mt) {
                int r  = wr0 + mt * 16 + lr;
                int cA = ks * 8 + lc;
                a[mt][0] = As[r * AP + cA];
                a[mt][1] = As[(r + 8) * AP + cA];
                a[mt][2] = As[r * AP + cA + 4];
                a[mt][3] = As[(r + 8) * AP + cA + 4];
            }
#pragma unroll
            for (int nt = 0; nt < 8; ++nt) {
                int bc = wc0 + nt * 8 + lr;
                int br = ks * 8 + lc;
                unsigned bb0 = Bs[br * BP + bc];
                unsigned bb1 = Bs[(br + 4) * BP + bc];
                mma8(acc[0][nt], a[0], bb0, bb1);
                mma8(acc[1][nt], a[1], bb0, bb1);
            }
        }
        __syncthreads();
    }

    // bias + SiLU -> Hs (stored pre-converted to tf32 for GEMM2 A-reads)
#pragma unroll
    for (int mt = 0; mt < 2; ++mt) {
#pragma unroll
        for (int nt = 0; nt < 8; ++nt) {
            int c  = wc0 + nt * 8 + 2 * lc;
            float2 bb = *(const float2*)&b0v[c];
            int r1 = wr0 + mt * 16 + lr;
            int r2 = r1 + 8;
            float x0 = acc[mt][nt][0] + bb.x;
            float x1 = acc[mt][nt][1] + bb.y;
            float x2 = acc[mt][nt][2] + bb.x;
            float x3 = acc[mt][nt][3] + bb.y;
            float s0 = x0 / (1.0f + __expf(-x0));
            float s1 = x1 / (1.0f + __expf(-x1));
            float s2 = x2 / (1.0f + __expf(-x2));
            float s3 = x3 / (1.0f + __expf(-x3));
            uint2 p1; p1.x = f2tf32(s0); p1.y = f2tf32(s1);
            uint2 p2; p2.x = f2tf32(s2); p2.y = f2tf32(s3);
            *(uint2*)&Hu[r1 * HP + c] = p1;
            *(uint2*)&Hu[r2 * HP + c] = p2;
        }
    }
    __syncthreads();

    // ---------------- GEMM2: y = H @ tf32(W1) ----------------
    float acc2[2][8][4];
#pragma unroll
    for (int m = 0; m < 2; ++m)
#pragma unroll
        for (int n = 0; n < 8; ++n)
#pragma unroll
            for (int j = 0; j < 4; ++j) acc2[m][n][j] = 0.0f;

#pragma unroll 1
    for (int kb = 0; kb < DD / KC; ++kb) {
#pragma unroll
        for (int j = 0; j < 8; ++j) {
            int row = rB + j * 2;
            Bs[row * BP + cB] = f2tf32(W1[(size_t)(kb * KC + row) * DD + cB]);
        }
        __syncthreads();

#pragma unroll
        for (int ks = 0; ks < 2; ++ks) {
            unsigned a[2][4];
            int cA = kb * KC + ks * 8 + lc;
#pragma unroll
            for (int mt = 0; mt < 2; ++mt) {
                int r = wr0 + mt * 16 + lr;
                a[mt][0] = Hu[r * HP + cA];
                a[mt][1] = Hu[(r + 8) * HP + cA];
                a[mt][2] = Hu[r * HP + cA + 4];
                a[mt][3] = Hu[(r + 8) * HP + cA + 4];
            }
#pragma unroll
            for (int nt = 0; nt < 8; ++nt) {
                int bc = wc0 + nt * 8 + lr;
                int br = ks * 8 + lc;
                unsigned bb0 = Bs[br * BP + bc];
                unsigned bb1 = Bs[(br + 4) * BP + bc];
                mma8(acc2[0][nt], a[0], bb0, bb1);
                mma8(acc2[1][nt], a[1], bb0, bb1);
            }
        }
        __syncthreads();
    }

    // y = acc2 + b1 -> Hs (fp32)
#pragma unroll
    for (int mt = 0; mt < 2; ++mt) {
#pragma unroll
        for (int nt = 0; nt < 8; ++nt) {
            int c  = wc0 + nt * 8 + 2 * lc;
            float2 bb = *(const float2*)&b1v[c];
            int r1 = wr0 + mt * 16 + lr;
            int r2 = r1 + 8;
            float2 y1; y1.x = acc2[mt][nt][0] + bb.x; y1.y = acc2[mt][nt][1] + bb.y;
            float2 y2; y2.x = acc2[mt][nt][2] + bb.x; y2.y = acc2[mt][nt][3] + bb.y;
            *(float2*)&Hs[r1 * HP + c] = y1;
            *(float2*)&Hs[r2 * HP + c] = y2;
        }
    }
    __syncthreads();

    // ---------------- LayerNorm + epilogue (warp w owns rows w*16..w*16+15) ----------------
    float4 gg = *(const float4*)&gamma[l * 4];
    float4 bt = *(const float4*)&beta[l * 4];

#pragma unroll 1
    for (int i = 0; i < 16; ++i) {
        int r  = wid * 16 + i;
        int rg = rowBase + r;
        float4 v = *(const float4*)&Hs[r * HP + l * 4];
        float s  = v.x + v.y + v.z + v.w;
        float ss = v.x * v.x + v.y * v.y + v.z * v.z + v.w * v.w;
#pragma unroll
        for (int off = 16; off > 0; off >>= 1) {
            s  += __shfl_xor_sync(0xFFFFFFFFu, s,  off);
            ss += __shfl_xor_sync(0xFFFFFFFFu, ss, off);
        }
        float mean = s * (1.0f / DD);
        float var  = ss * (1.0f / DD) - mean * mean;
        float rstd = rsqrtf(var + 1e-5f);

        float4 o;
        o.x = (v.x - mean) * rstd * gg.x + bt.x;
        o.y = (v.y - mean) * rstd * gg.y + bt.y;
        o.z = (v.z - mean) * rstd * gg.z + bt.z;
        o.w = (v.w - mean) * rstd * gg.w + bt.w;

        if (MODE == 0) {
            if (rg < R) {
                float* p = &agg[(size_t)Id[r] * DD + l * 4];
                asm volatile("red.global.add.v4.f32 [%0], {%1,%2,%3,%4};"
                             :: "l"(p), "f"(o.x), "f"(o.y), "f"(o.z), "f"(o.w)
                             : "memory");
            }
        } else {
            if (rg < R) {
                float4 rv = *(const float4*)&resid[(size_t)rg * DD + l * 4];
                o.x += rv.x; o.y += rv.y; o.z += rv.z; o.w += rv.w;
                *(float4*)&out[(size_t)rg * DD + l * 4] = o;
            }
        }
    }
}

extern "C" void kernel_launch(void* const* d_in, const int* in_sizes, int n_in,
                              void* d_out, int out_size)
{
    const float* efeat   = (const float*)d_in[0];
    const float* grid    = (const float*)d_in[1];
    const float* mesh    = (const float*)d_in[2];
    const int*   src_idx = (const int*)d_in[3];
    const int*   dst_idx = (const int*)d_in[4];
    const float* eW0 = (const float*)d_in[5];
    const float* eb0 = (const float*)d_in[6];
    const float* eW1 = (const float*)d_in[7];
    const float* eb1 = (const float*)d_in[8];
    const float* eg  = (const float*)d_in[9];
    const float* ebt = (const float*)d_in[10];
    const float* sW0 = (const float*)d_in[11];
    const float* sb0 = (const float*)d_in[12];
    const float* sW1 = (const float*)d_in[13];
    const float* sb1 = (const float*)d_in[14];
    const float* sg  = (const float*)d_in[15];
    const float* sbt = (const float*)d_in[16];
    const float* dW0 = (const float*)d_in[17];
    const float* db0 = (const float*)d_in[18];
    const float* dW1 = (const float*)d_in[19];
    const float* db1 = (const float*)d_in[20];
    const float* dg  = (const float*)d_in[21];
    const float* dbt = (const float*)d_in[22];

    float* out_grid = (float*)d_out;                       // [NG, 128]
    float* out_mesh = (float*)d_out + (size_t)NG * DD;     // [NM, 128]

    float* agg_ptr = nullptr;
    cudaGetSymbolAddress((void**)&agg_ptr, g_agg);

    static bool attr_done = false;
    if (!attr_done) {
        cudaFuncSetAttribute(mlp_tc<384, 0>, cudaFuncAttributeMaxDynamicSharedMemorySize, SMEM_BYTES);
        cudaFuncSetAttribute(mlp_tc<128, 1>, cudaFuncAttributeMaxDynamicSharedMemorySize, SMEM_BYTES);
        cudaFuncSetAttribute(mlp_tc<256, 2>, cudaFuncAttributeMaxDynamicSharedMemorySize, SMEM_BYTES);
        attr_done = true;
    }

    // 1) zero the scatter accumulator
    zero_agg_kernel<<<512, 256>>>();

    // 2) edge MLP + scatter-sum
    {
        int blocks = NE / BLK_R;  // 4096
        mlp_tc<384, 0><<<blocks, NTH, SMEM_BYTES>>>(
            efeat, grid, mesh, src_idx, dst_idx,
            eW0, eb0, eW1, eb1, eg, ebt,
            nullptr, nullptr, agg_ptr, NE);
    }

    // 3) src (grid) node MLP with residual
    {
        int blocks = NG / BLK_R;  // 1024
        mlp_tc<128, 1><<<blocks, NTH, SMEM_BYTES>>>(
            grid, nullptr, nullptr, nullptr, nullptr,
            sW0, sb0, sW1, sb1, sg, sbt,
            grid, out_grid, nullptr, NG);
    }

    // 4) dst (mesh) node MLP with residual (depends on edge scatter)
    {
        int blocks = (NM + BLK_R - 1) / BLK_R;  // 321
        mlp_tc<256, 2><<<blocks, NTH, SMEM_BYTES>>>(
            agg_ptr, mesh, nullptr, nullptr, nullptr,
            dW0, db0, dW1, db1, dg, dbt,
            mesh, out_mesh, nullptr, NM);
    }
}

// round 4
// speedup vs baseline: 5.3151x; 2.6787x over previous
#include <cuda_runtime.h>
#include <math.h>

#define NG 131072
#define NM 40962
#define NE 524288
#define DD 128

#define BLK_R 128
#define KC 32
#define NTH 256

#define AP 36    // As pitch (fp32 elems), conflict-free frag reads
#define BP 136   // Bs pitch
#define HP 132   // Hs pitch

// smem byte offsets
#define ASZ 18432          // 128*36*4 per A buffer
#define BSZ 17408          // 32*136*4 per B buffer
#define OFF_AS 0           // two A buffers: 0..36864 (overlapped by Hs later)
#define OFF_HS 0           // Hs: 128*132*4 = 67584  (valid only after GEMM1)
#define OFF_BS 67584       // two B buffers: 67584..102400
#define OFF_IS 102400
#define OFF_ID 102912
#define SMEM_BYTES 103424

// scatter-sum accumulator for edge messages -> mesh nodes
__device__ float g_agg[(size_t)NM * DD];
// tf32-pre-rounded weights: eW0,eW1,sW0,sW1,dW0,dW1
__device__ float g_w[147456];

__device__ __forceinline__ unsigned f2tf32(float x) {
    unsigned u;
    asm("cvt.rna.tf32.f32 %0, %1;" : "=r"(u) : "f"(x));
    return u;
}

__global__ void zero_agg_kernel() {
    size_t n = (size_t)NM * DD / 4;
    float4 z = make_float4(0.f, 0.f, 0.f, 0.f);
    float4* p = (float4*)g_agg;
    for (size_t i = blockIdx.x * (size_t)blockDim.x + threadIdx.x; i < n;
         i += (size_t)gridDim.x * blockDim.x) p[i] = z;
}

__global__ void prep_weights(const float* __restrict__ eW0, const float* __restrict__ eW1,
                             const float* __restrict__ sW0, const float* __restrict__ sW1,
                             const float* __restrict__ dW0, const float* __restrict__ dW1) {
    int i = blockIdx.x * blockDim.x + threadIdx.x;
    float v;
    if (i < 49152)        v = eW0[i];
    else if (i < 65536)   v = eW1[i - 49152];
    else if (i < 81920)   v = sW0[i - 65536];
    else if (i < 98304)   v = sW1[i - 81920];
    else if (i < 131072)  v = dW0[i - 98304];
    else                  v = dW1[i - 131072];
    g_w[i] = __uint_as_float(f2tf32(v));
}

__device__ __forceinline__ void cp16(unsigned saddr, const void* g, bool pred) {
    int sz = pred ? 16 : 0;
    asm volatile("cp.async.cg.shared.global [%0], [%1], 16, %2;\n"
                 :: "r"(saddr), "l"(g), "r"(sz));
}
#define CP_COMMIT asm volatile("cp.async.commit_group;\n")
template <int N>
__device__ __forceinline__ void cp_wait() {
    asm volatile("cp.async.wait_group %0;\n" :: "n"(N));
}

__device__ __forceinline__ void mma8(float* d, const unsigned* a, unsigned b0, unsigned b1) {
    asm volatile(
        "mma.sync.aligned.m16n8k8.row.col.f32.tf32.tf32.f32 "
        "{%0,%1,%2,%3}, {%4,%5,%6,%7}, {%8,%9}, {%0,%1,%2,%3};\n"
        : "+f"(d[0]), "+f"(d[1]), "+f"(d[2]), "+f"(d[3])
        : "r"(a[0]), "r"(a[1]), "r"(a[2]), "r"(a[3]), "r"(b0), "r"(b1));
}

// MODE 0: edge MLP  (concat(efeat, grid[src], mesh[dst]) -> red.v4 scatter into agg[dst])
// MODE 1: plain MLP (Xa -> resid + out)
// MODE 2: dst MLP   (concat(agg, mesh) -> resid + out)
template <int K1, int MODE>
__global__ __launch_bounds__(NTH, 2)
void mlp_tc(const float* __restrict__ Xa,
            const float* __restrict__ Xb,
            const float* __restrict__ Xc,
            const int* __restrict__ src_idx,
            const int* __restrict__ dst_idx,
            const float* __restrict__ W0r, const float* __restrict__ b0v,
            const float* __restrict__ W1r, const float* __restrict__ b1v,
            const float* __restrict__ gamma, const float* __restrict__ beta,
            const float* __restrict__ resid,
            float* __restrict__ out,
            float* __restrict__ agg,
            int R)
{
    extern __shared__ unsigned char smem[];
    float*    Hs = (float*)(smem + OFF_HS);
    unsigned* Hu = (unsigned*)(smem + OFF_HS);
    int*      Is = (int*)(smem + OFF_IS);
    int*      Id = (int*)(smem + OFF_ID);
    const unsigned sbase = (unsigned)__cvta_generic_to_shared(smem);

    const int t   = threadIdx.x;
    const int wid = t >> 5;
    const int l   = t & 31;
    const int lr  = l >> 2;
    const int lc  = l & 3;
    const int warpM = wid >> 1;
    const int warpN = wid & 1;
    const int wr0 = warpM * 32;
    const int wc0 = warpN * 64;
    const int rowBase = blockIdx.x * BLK_R;

    if (MODE == 0) {
        if (t < 128) {
            Is[t] = src_idx[rowBase + t];
            Id[t] = dst_idx[rowBase + t];
        }
        __syncthreads();
    }

    // ---- async tile loaders ----
    const int ac4 = (t & 7) * 4;   // A col (float)
    const int arr = t >> 3;        // A row base (0..31)
    const int bc4 = (t & 31) * 4;  // B col
    const int br0 = t >> 5;        // B row base (0..7)

    auto load_a = [&](int k0, int buf) {
#pragma unroll
        for (int j = 0; j < 4; ++j) {
            int r  = arr + j * 32;
            int rg = rowBase + r;
            bool pred = (MODE == 0) ? true : (rg < R);
            int rgc = pred ? rg : (R - 1);
            const float* src;
            if (MODE == 0) {
                int seg = k0 >> 7;
                int cc  = (k0 & 127) + ac4;
                src = (seg == 0) ? Xa + (size_t)rg * 128 + cc
                    : (seg == 1) ? Xb + (size_t)Is[r] * 128 + cc
                                 : Xc + (size_t)Id[r] * 128 + cc;
            } else if (MODE == 1) {
                src = Xa + (size_t)rgc * 128 + k0 + ac4;
            } else {
                int seg = k0 >> 7;
                int cc  = (k0 & 127) + ac4;
                src = (seg == 0) ? Xa + (size_t)rgc * 128 + cc
                                 : Xb + (size_t)rgc * 128 + cc;
            }
            cp16(sbase + OFF_AS + buf * ASZ + (unsigned)(r * AP + ac4) * 4u, src, pred);
        }
    };
    auto load_b = [&](const float* W, int k0, int buf) {
#pragma unroll
        for (int j = 0; j < 4; ++j) {
            int r = br0 + j * 8;
            cp16(sbase + OFF_BS + buf * BSZ + (unsigned)(r * BP + bc4) * 4u,
                 W + (size_t)(k0 + r) * 128 + bc4, true);
        }
    };

    // ---------------- GEMM1: acc = tf32(X) @ W0r ----------------
    float acc[2][8][4];
#pragma unroll
    for (int m = 0; m < 2; ++m)
#pragma unroll
        for (int n = 0; n < 8; ++n)
#pragma unroll
            for (int j = 0; j < 4; ++j) acc[m][n][j] = 0.0f;

    constexpr int NCH1 = K1 / KC;
    load_a(0, 0); load_b(W0r, 0, 0); CP_COMMIT;

#pragma unroll 1
    for (int kb = 0; kb < NCH1; ++kb) {
        cp_wait<0>();
        __syncthreads();
        if (kb + 1 < NCH1) {
            load_a((kb + 1) * KC, (kb + 1) & 1);
            load_b(W0r, (kb + 1) * KC, (kb + 1) & 1);
            CP_COMMIT;
        }
        const float*    Af = (const float*)(smem + OFF_AS + (kb & 1) * ASZ);
        const unsigned* Bu = (const unsigned*)(smem + OFF_BS + (kb & 1) * BSZ);
#pragma unroll
        for (int ks = 0; ks < 4; ++ks) {
            unsigned a[2][4];
#pragma unroll
            for (int mt = 0; mt < 2; ++mt) {
                int r  = wr0 + mt * 16 + lr;
                int cA = ks * 8 + lc;
                a[mt][0] = f2tf32(Af[r * AP + cA]);
                a[mt][1] = f2tf32(Af[(r + 8) * AP + cA]);
                a[mt][2] = f2tf32(Af[r * AP + cA + 4]);
                a[mt][3] = f2tf32(Af[(r + 8) * AP + cA + 4]);
            }
#pragma unroll
            for (int nt = 0; nt < 8; ++nt) {
                int bc = wc0 + nt * 8 + lr;
                int br = ks * 8 + lc;
                unsigned bb0 = Bu[br * BP + bc];
                unsigned bb1 = Bu[(br + 4) * BP + bc];
                mma8(acc[0][nt], a[0], bb0, bb1);
                mma8(acc[1][nt], a[1], bb0, bb1);
            }
        }
        __syncthreads();  // protect A/B buffers before next prefetch lands / reuse
    }

    // bias + SiLU -> Hs (tf32 bits; region overlaps dead A buffers)
#pragma unroll
    for (int mt = 0; mt < 2; ++mt) {
#pragma unroll
        for (int nt = 0; nt < 8; ++nt) {
            int c  = wc0 + nt * 8 + 2 * lc;
            float2 bb = *(const float2*)&b0v[c];
            int r1 = wr0 + mt * 16 + lr;
            int r2 = r1 + 8;
            float x0 = acc[mt][nt][0] + bb.x;
            float x1 = acc[mt][nt][1] + bb.y;
            float x2 = acc[mt][nt][2] + bb.x;
            float x3 = acc[mt][nt][3] + bb.y;
            float s0 = x0 / (1.0f + __expf(-x0));
            float s1 = x1 / (1.0f + __expf(-x1));
            float s2 = x2 / (1.0f + __expf(-x2));
            float s3 = x3 / (1.0f + __expf(-x3));
            uint2 p1; p1.x = f2tf32(s0); p1.y = f2tf32(s1);
            uint2 p2; p2.x = f2tf32(s2); p2.y = f2tf32(s3);
            *(uint2*)&Hu[r1 * HP + c] = p1;
            *(uint2*)&Hu[r2 * HP + c] = p2;
        }
    }
    __syncthreads();

    // ---------------- GEMM2: y = H @ W1r ----------------
    float acc2[2][8][4];
#pragma unroll
    for (int m = 0; m < 2; ++m)
#pragma unroll
        for (int n = 0; n < 8; ++n)
#pragma unroll
            for (int j = 0; j < 4; ++j) acc2[m][n][j] = 0.0f;

    load_b(W1r, 0, 0); CP_COMMIT;
#pragma unroll 1
    for (int kb = 0; kb < 4; ++kb) {
        cp_wait<0>();
        __syncthreads();
        if (kb + 1 < 4) { load_b(W1r, (kb + 1) * KC, (kb + 1) & 1); CP_COMMIT; }
        const unsigned* Bu = (const unsigned*)(smem + OFF_BS + (kb & 1) * BSZ);
#pragma unroll
        for (int ks = 0; ks < 4; ++ks) {
            unsigned a[2][4];
            int cA = kb * KC + ks * 8 + lc;
#pragma unroll
            for (int mt = 0; mt < 2; ++mt) {
                int r = wr0 + mt * 16 + lr;
                a[mt][0] = Hu[r * HP + cA];
                a[mt][1] = Hu[(r + 8) * HP + cA];
                a[mt][2] = Hu[r * HP + cA + 4];
                a[mt][3] = Hu[(r + 8) * HP + cA + 4];
            }
#pragma unroll
            for (int nt = 0; nt < 8; ++nt) {
                int bc = wc0 + nt * 8 + lr;
                int br = ks * 8 + lc;
                unsigned bb0 = Bu[br * BP + bc];
                unsigned bb1 = Bu[(br + 4) * BP + bc];
                mma8(acc2[0][nt], a[0], bb0, bb1);
                mma8(acc2[1][nt], a[1], bb0, bb1);
            }
        }
        __syncthreads();
    }

    // y = acc2 + b1 -> Hs (fp32)
#pragma unroll
    for (int mt = 0; mt < 2; ++mt) {
#pragma unroll
        for (int nt = 0; nt < 8; ++nt) {
            int c  = wc0 + nt * 8 + 2 * lc;
            float2 bb = *(const float2*)&b1v[c];
            int r1 = wr0 + mt * 16 + lr;
            int r2 = r1 + 8;
            float2 y1; y1.x = acc2[mt][nt][0] + bb.x; y1.y = acc2[mt][nt][1] + bb.y;
            float2 y2; y2.x = acc2[mt][nt][2] + bb.x; y2.y = acc2[mt][nt][3] + bb.y;
            *(float2*)&Hs[r1 * HP + c] = y1;
            *(float2*)&Hs[r2 * HP + c] = y2;
        }
    }
    __syncthreads();

    // ---------------- LayerNorm + epilogue ----------------
    float4 gg = *(const float4*)&gamma[l * 4];
    float4 bt = *(const float4*)&beta[l * 4];

#pragma unroll 1
    for (int i = 0; i < 16; ++i) {
        int r  = wid * 16 + i;
        int rg = rowBase + r;
        float4 v = *(const float4*)&Hs[r * HP + l * 4];
        float s  = v.x + v.y + v.z + v.w;
        float ss = v.x * v.x + v.y * v.y + v.z * v.z + v.w * v.w;
#pragma unroll
        for (int off = 16; off > 0; off >>= 1) {
            s  += __shfl_xor_sync(0xFFFFFFFFu, s,  off);
            ss += __shfl_xor_sync(0xFFFFFFFFu, ss, off);
        }
        float mean = s * (1.0f / DD);
        float var  = ss * (1.0f / DD) - mean * mean;
        float rstd = rsqrtf(var + 1e-5f);

        float4 o;
        o.x = (v.x - mean) * rstd * gg.x + bt.x;
        o.y = (v.y - mean) * rstd * gg.y + bt.y;
        o.z = (v.z - mean) * rstd * gg.z + bt.z;
        o.w = (v.w - mean) * rstd * gg.w + bt.w;

        if (MODE == 0) {
            float* p = &agg[(size_t)Id[r] * DD + l * 4];
            asm volatile("red.global.add.v4.f32 [%0], {%1,%2,%3,%4};"
                         :: "l"(p), "f"(o.x), "f"(o.y), "f"(o.z), "f"(o.w)
                         : "memory");
        } else {
            if (rg < R) {
                float4 rv = *(const float4*)&resid[(size_t)rg * DD + l * 4];
                o.x += rv.x; o.y += rv.y; o.z += rv.z; o.w += rv.w;
                *(float4*)&out[(size_t)rg * DD + l * 4] = o;
            }
        }
    }
}

extern "C" void kernel_launch(void* const* d_in, const int* in_sizes, int n_in,
                              void* d_out, int out_size)
{
    const float* efeat   = (const float*)d_in[0];
    const float* grid    = (const float*)d_in[1];
    const float* mesh    = (const float*)d_in[2];
    const int*   src_idx = (const int*)d_in[3];
    const int*   dst_idx = (const int*)d_in[4];
    const float* eW0 = (const float*)d_in[5];
    const float* eb0 = (const float*)d_in[6];
    const float* eW1 = (const float*)d_in[7];
    const float* eb1 = (const float*)d_in[8];
    const float* eg  = (const float*)d_in[9];
    const float* ebt = (const float*)d_in[10];
    const float* sW0 = (const float*)d_in[11];
    const float* sb0 = (const float*)d_in[12];
    const float* sW1 = (const float*)d_in[13];
    const float* sb1 = (const float*)d_in[14];
    const float* sg  = (const float*)d_in[15];
    const float* sbt = (const float*)d_in[16];
    const float* dW0 = (const float*)d_in[17];
    const float* db0 = (const float*)d_in[18];
    const float* dW1 = (const float*)d_in[19];
    const float* db1 = (const float*)d_in[20];
    const float* dg  = (const float*)d_in[21];
    const float* dbt = (const float*)d_in[22];

    float* out_grid = (float*)d_out;
    float* out_mesh = (float*)d_out + (size_t)NG * DD;

    float* agg_ptr = nullptr;
    cudaGetSymbolAddress((void**)&agg_ptr, g_agg);
    float* w_ptr = nullptr;
    cudaGetSymbolAddress((void**)&w_ptr, g_w);

    static bool attr_done = false;
    if (!attr_done) {
        cudaFuncSetAttribute(mlp_tc<384, 0>, cudaFuncAttributeMaxDynamicSharedMemorySize, SMEM_BYTES);
        cudaFuncSetAttribute(mlp_tc<128, 1>, cudaFuncAttributeMaxDynamicSharedMemorySize, SMEM_BYTES);
        cudaFuncSetAttribute(mlp_tc<256, 2>, cudaFuncAttributeMaxDynamicSharedMemorySize, SMEM_BYTES);
        attr_done = true;
    }

    // 0) pre-round weights to tf32 + zero scatter accumulator
    prep_weights<<<576, 256>>>(eW0, eW1, sW0, sW1, dW0, dW1);
    zero_agg_kernel<<<512, 256>>>();

    const float* weW0 = w_ptr;
    const float* weW1 = w_ptr + 49152;
    const float* wsW0 = w_ptr + 65536;
    const float* wsW1 = w_ptr + 81920;
    const float* wdW0 = w_ptr + 98304;
    const float* wdW1 = w_ptr + 131072;

    // 1) edge MLP + scatter-sum
    mlp_tc<384, 0><<<NE / BLK_R, NTH, SMEM_BYTES>>>(
        efeat, grid, mesh, src_idx, dst_idx,
        weW0, eb0, weW1, eb1, eg, ebt,
        nullptr, nullptr, agg_ptr, NE);

    // 2) src (grid) node MLP with residual
    mlp_tc<128, 1><<<NG / BLK_R, NTH, SMEM_BYTES>>>(
        grid, nullptr, nullptr, nullptr, nullptr,
        wsW0, sb0, wsW1, sb1, sg, sbt,
        grid, out_grid, nullptr, NG);

    // 3) dst (mesh) node MLP with residual
    mlp_tc<256, 2><<<(NM + BLK_R - 1) / BLK_R, NTH, SMEM_BYTES>>>(
        agg_ptr, mesh, nullptr, nullptr, nullptr,
        wdW0, db0, wdW1, db1, dg, dbt,
        mesh, out_mesh, nullptr, NM);
}

// round 7
// speedup vs baseline: 6.7265x; 1.2656x over previous
#include <cuda_runtime.h>
#include <cuda_fp16.h>
#include <math.h>

#define NG 131072
#define NM 40962
#define NE 524288
#define DD 128

#define BLK_R 128
#define KC 32
#define NTH 256

#define AP 40     // A pitch (fp32 elems)
#define BPh 40    // B pitch (half elems)
#define HPh 136   // H pitch (half elems)
#define YP 132    // Y pitch (fp32 elems)

#define ASZ 20480            // 128*40*4 per A buffer
#define BSZ 10240            // 128*40*2 per B buffer
#define OFF_AS 0             // A bufs: 0..40960   (Hs overlaps after GEMM1)
#define OFF_HS 0             // Hs half: 128*136*2 = 34816
#define OFF_BS 40960         // B bufs: 40960..61440
#define OFF_Y  0             // Y fp32: 128*132*4 = 67584 (valid after GEMM2)
#define OFF_IS 67584
#define OFF_ID 68096
#define SMEM_BYTES 68608

__device__ float g_agg[(size_t)NM * DD];
// fp16 transposed weights: eW0t(128x384), eW1t(128x128), sW0t, sW1t, dW0t(128x256), dW1t
__device__ __half g_wh[147456];

__global__ void zero_agg_kernel() {
    size_t n = (size_t)NM * DD / 4;
    float4 z = make_float4(0.f, 0.f, 0.f, 0.f);
    float4* p = (float4*)g_agg;
    for (size_t i = blockIdx.x * (size_t)blockDim.x + threadIdx.x; i < n;
         i += (size_t)gridDim.x * blockDim.x) p[i] = z;
}

__global__ void prep_weights(const float* __restrict__ eW0, const float* __restrict__ eW1,
                             const float* __restrict__ sW0, const float* __restrict__ sW1,
                             const float* __restrict__ dW0, const float* __restrict__ dW1) {
    int i = blockIdx.x * blockDim.x + threadIdx.x;
    if (i >= 147456) return;
    float v;
    if (i < 49152)       { int j = i;          v = eW0[(j % 384) * 128 + (j / 384)]; }
    else if (i < 65536)  { int j = i - 49152;  v = eW1[(j % 128) * 128 + (j / 128)]; }
    else if (i < 81920)  { int j = i - 65536;  v = sW0[(j % 128) * 128 + (j / 128)]; }
    else if (i < 98304)  { int j = i - 81920;  v = sW1[(j % 128) * 128 + (j / 128)]; }
    else if (i < 131072) { int j = i - 98304;  v = dW0[(j % 256) * 128 + (j / 256)]; }
    else                 { int j = i - 131072; v = dW1[(j % 128) * 128 + (j / 128)]; }
    g_wh[i] = __float2half_rn(v);
}

__device__ __forceinline__ void cp16(unsigned saddr, const void* g, bool pred) {
    int sz = pred ? 16 : 0;
    asm volatile("cp.async.cg.shared.global [%0], [%1], 16, %2;\n"
                 :: "r"(saddr), "l"(g), "r"(sz));
}
#define CP_COMMIT asm volatile("cp.async.commit_group;\n")
template <int N>
__device__ __forceinline__ void cp_wait() {
    asm volatile("cp.async.wait_group %0;\n" :: "n"(N));
}

__device__ __forceinline__ unsigned packh2(float lo, float hi) {
    unsigned r;
    asm("cvt.rn.f16x2.f32 %0, %1, %2;" : "=r"(r) : "f"(hi), "f"(lo));
    return r;
}

__device__ __forceinline__ void mma16(float* d, const unsigned* a, unsigned b0, unsigned b1) {
    asm volatile(
        "mma.sync.aligned.m16n8k16.row.col.f32.f16.f16.f32 "
        "{%0,%1,%2,%3}, {%4,%5,%6,%7}, {%8,%9}, {%0,%1,%2,%3};\n"
        : "+f"(d[0]), "+f"(d[1]), "+f"(d[2]), "+f"(d[3])
        : "r"(a[0]), "r"(a[1]), "r"(a[2]), "r"(a[3]), "r"(b0), "r"(b1));
}

// MODE 0: edge MLP  (concat(efeat, grid[src], mesh[dst]) -> red.v4 scatter into agg[dst])
// MODE 1: plain MLP (Xa -> resid + out)
// MODE 2: dst MLP   (concat(agg, mesh) -> resid + out)
template <int K1, int MODE>
__global__ __launch_bounds__(NTH, 2)
void mlp_tc(const float* __restrict__ Xa,
            const float* __restrict__ Xb,
            const float* __restrict__ Xc,
            const int* __restrict__ src_idx,
            const int* __restrict__ dst_idx,
            const __half* __restrict__ W0t, const float* __restrict__ b0v,
            const __half* __restrict__ W1t, const float* __restrict__ b1v,
            const float* __restrict__ gamma, const float* __restrict__ beta,
            const float* __restrict__ resid,
            float* __restrict__ out,
            float* __restrict__ agg,
            int R)
{
    extern __shared__ unsigned char smem[];
    unsigned* Hu = (unsigned*)(smem + OFF_HS);   // H as f16x2 words
    float*    Ys = (float*)(smem + OFF_Y);
    int*      Is = (int*)(smem + OFF_IS);
    int*      Id = (int*)(smem + OFF_ID);
    const unsigned sbase = (unsigned)__cvta_generic_to_shared(smem);

    const int t   = threadIdx.x;
    const int wid = t >> 5;
    const int l   = t & 31;
    const int lr  = l >> 2;
    const int lc  = l & 3;
    const int warpM = wid >> 1;
    const int warpN = wid & 1;
    const int wr0 = warpM * 32;
    const int wc0 = warpN * 64;
    const int rowBase = blockIdx.x * BLK_R;

    if (MODE == 0) {
        if (t < 128) {
            Is[t] = src_idx[rowBase + t];
            Id[t] = dst_idx[rowBase + t];
        }
        __syncthreads();
    }

    // ---- async tile loaders ----
    const int ac4 = (t & 7) * 4;   // A col (float)
    const int arr = t >> 3;        // A row base (0..31)

    auto load_a = [&](int k0, int buf) {
#pragma unroll
        for (int j = 0; j < 4; ++j) {
            int r  = arr + j * 32;
            int rg = rowBase + r;
            bool pred = (MODE == 0) ? true : (rg < R);
            int rgc = pred ? rg : (R - 1);
            const float* src;
            if (MODE == 0) {
                int seg = k0 >> 7;
                int cc  = (k0 & 127) + ac4;
                src = (seg == 0) ? Xa + (size_t)rg * 128 + cc
                    : (seg == 1) ? Xb + (size_t)Is[r] * 128 + cc
                                 : Xc + (size_t)Id[r] * 128 + cc;
            } else if (MODE == 1) {
                src = Xa + (size_t)rgc * 128 + k0 + ac4;
            } else {
                int seg = k0 >> 7;
                int cc  = (k0 & 127) + ac4;
                src = (seg == 0) ? Xa + (size_t)rgc * 128 + cc
                                 : Xb + (size_t)rgc * 128 + cc;
            }
            cp16(sbase + OFF_AS + buf * ASZ + (unsigned)(r * AP + ac4) * 4u, src, pred);
        }
    };
    // B tile: 128 rows (n) x 32 halves (k); 512 cp16 -> 2 per thread
    auto load_b = [&](const __half* Wt, int KS, int k0, int buf) {
#pragma unroll
        for (int j = 0; j < 2; ++j) {
            int idx = t + j * 256;
            int n = idx >> 2;
            int ch = idx & 3;
            cp16(sbase + OFF_BS + buf * BSZ + (unsigned)(n * BPh * 2 + ch * 16),
                 Wt + (size_t)n * KS + k0 + ch * 8, true);
        }
    };

    // ---------------- GEMM1: acc = f16(X) @ W0t ----------------
    float acc[2][8][4];
#pragma unroll
    for (int m = 0; m < 2; ++m)
#pragma unroll
        for (int n = 0; n < 8; ++n)
#pragma unroll
            for (int j = 0; j < 4; ++j) acc[m][n][j] = 0.0f;

    constexpr int NCH1 = K1 / KC;
    load_a(0, 0); load_b(W0t, K1, 0, 0); CP_COMMIT;

#pragma unroll 1
    for (int kb = 0; kb < NCH1; ++kb) {
        cp_wait<0>();
        __syncthreads();
        if (kb + 1 < NCH1) {
            load_a((kb + 1) * KC, (kb + 1) & 1);
            load_b(W0t, K1, (kb + 1) * KC, (kb + 1) & 1);
            CP_COMMIT;
        }
        const float*    Af = (const float*)(smem + OFF_AS + (kb & 1) * ASZ);
        const unsigned* Bu = (const unsigned*)(smem + OFF_BS + (kb & 1) * BSZ);
#pragma unroll
        for (int ks = 0; ks < 2; ++ks) {
            unsigned a[2][4];
            int c0 = ks * 16 + 2 * lc;
#pragma unroll
            for (int mt = 0; mt < 2; ++mt) {
                int r = wr0 + mt * 16 + lr;
                float2 f0 = *(const float2*)&Af[r * AP + c0];
                float2 f1 = *(const float2*)&Af[(r + 8) * AP + c0];
                float2 f2 = *(const float2*)&Af[r * AP + c0 + 8];
                float2 f3 = *(const float2*)&Af[(r + 8) * AP + c0 + 8];
                a[mt][0] = packh2(f0.x, f0.y);
                a[mt][1] = packh2(f1.x, f1.y);
                a[mt][2] = packh2(f2.x, f2.y);
                a[mt][3] = packh2(f3.x, f3.y);
            }
#pragma unroll
            for (int nt = 0; nt < 8; ++nt) {
                int n = wc0 + nt * 8 + lr;
                unsigned bb0 = Bu[n * (BPh / 2) + ks * 8 + lc];
                unsigned bb1 = Bu[n * (BPh / 2) + ks * 8 + lc + 4];
                mma16(acc[0][nt], a[0], bb0, bb1);
                mma16(acc[1][nt], a[1], bb0, bb1);
            }
        }
        __syncthreads();
    }

    // bias + SiLU -> H (fp16, overlaps dead A buffers)
#pragma unroll
    for (int mt = 0; mt < 2; ++mt) {
#pragma unroll
        for (int nt = 0; nt < 8; ++nt) {
            int c  = wc0 + nt * 8 + 2 * lc;
            float2 bb = *(const float2*)&b0v[c];
            int r1 = wr0 + mt * 16 + lr;
            int r2 = r1 + 8;
            float x0 = acc[mt][nt][0] + bb.x;
            float x1 = acc[mt][nt][1] + bb.y;
            float x2 = acc[mt][nt][2] + bb.x;
            float x3 = acc[mt][nt][3] + bb.y;
            float s0 = x0 / (1.0f + __expf(-x0));
            float s1 = x1 / (1.0f + __expf(-x1));
            float s2 = x2 / (1.0f + __expf(-x2));
            float s3 = x3 / (1.0f + __expf(-x3));
            Hu[(r1 * HPh + c) >> 1] = packh2(s0, s1);
            Hu[(r2 * HPh + c) >> 1] = packh2(s2, s3);
        }
    }
    __syncthreads();

    // ---------------- GEMM2: y = H @ W1t ----------------
    float acc2[2][8][4];
#pragma unroll
    for (int m = 0; m < 2; ++m)
#pragma unroll
        for (int n = 0; n < 8; ++n)
#pragma unroll
            for (int j = 0; j < 4; ++j) acc2[m][n][j] = 0.0f;

    load_b(W1t, 128, 0, 0); CP_COMMIT;
#pragma unroll 1
    for (int kb = 0; kb < 4; ++kb) {
        cp_wait<0>();
        __syncthreads();
        if (kb + 1 < 4) { load_b(W1t, 128, (kb + 1) * KC, (kb + 1) & 1); CP_COMMIT; }
        const unsigned* Bu = (const unsigned*)(smem + OFF_BS + (kb & 1) * BSZ);
#pragma unroll
        for (int ks = 0; ks < 2; ++ks) {
            unsigned a[2][4];
            int kk = kb * 16 + ks * 8 + lc;   // f16x2-word index along k
#pragma unroll
            for (int mt = 0; mt < 2; ++mt) {
                int r = wr0 + mt * 16 + lr;
                a[mt][0] = Hu[r * (HPh / 2) + kk];
                a[mt][1] = Hu[(r + 8) * (HPh / 2) + kk];
                a[mt][2] = Hu[r * (HPh / 2) + kk + 4];
                a[mt][3] = Hu[(r + 8) * (HPh / 2) + kk + 4];
            }
#pragma unroll
            for (int nt = 0; nt < 8; ++nt) {
                int n = wc0 + nt * 8 + lr;
                unsigned bb0 = Bu[n * (BPh / 2) + ks * 8 + lc];
                unsigned bb1 = Bu[n * (BPh / 2) + ks * 8 + lc + 4];
                mma16(acc2[0][nt], a[0], bb0, bb1);
                mma16(acc2[1][nt], a[1], bb0, bb1);
            }
        }
        __syncthreads();
    }

    // y = acc2 + b1 -> Y (fp32; overlaps A/H/B regions, all dead now)
#pragma unroll
    for (int mt = 0; mt < 2; ++mt) {
#pragma unroll
        for (int nt = 0; nt < 8; ++nt) {
            int c  = wc0 + nt * 8 + 2 * lc;
            float2 bb = *(const float2*)&b1v[c];
            int r1 = wr0 + mt * 16 + lr;
            int r2 = r1 + 8;
            float2 y1; y1.x = acc2[mt][nt][0] + bb.x; y1.y = acc2[mt][nt][1] + bb.y;
            float2 y2; y2.x = acc2[mt][nt][2] + bb.x; y2.y = acc2[mt][nt][3] + bb.y;
            *(float2*)&Ys[r1 * YP + c] = y1;
            *(float2*)&Ys[r2 * YP + c] = y2;
        }
    }
    __syncthreads();

    // ---------------- LayerNorm + epilogue ----------------
    float4 gg = *(const float4*)&gamma[l * 4];
    float4 bt = *(const float4*)&beta[l * 4];

#pragma unroll 1
    for (int i = 0; i < 16; ++i) {
        int r  = wid * 16 + i;
        int rg = rowBase + r;
        float4 v = *(const float4*)&Ys[r * YP + l * 4];
        float s  = v.x + v.y + v.z + v.w;
        float ss = v.x * v.x + v.y * v.y + v.z * v.z + v.w * v.w;
#pragma unroll
        for (int off = 16; off > 0; off >>= 1) {
            s  += __shfl_xor_sync(0xFFFFFFFFu, s,  off);
            ss += __shfl_xor_sync(0xFFFFFFFFu, ss, off);
        }
        float mean = s * (1.0f / DD);
        float var  = ss * (1.0f / DD) - mean * mean;
        float rstd = rsqrtf(var + 1e-5f);

        float4 o;
        o.x = (v.x - mean) * rstd * gg.x + bt.x;
        o.y = (v.y - mean) * rstd * gg.y + bt.y;
        o.z = (v.z - mean) * rstd * gg.z + bt.z;
        o.w = (v.w - mean) * rstd * gg.w + bt.w;

        if (MODE == 0) {
            float* p = &agg[(size_t)Id[r] * DD + l * 4];
            asm volatile("red.global.add.v4.f32 [%0], {%1,%2,%3,%4};"
                         :: "l"(p), "f"(o.x), "f"(o.y), "f"(o.z), "f"(o.w)
                         : "memory");
        } else {
            if (rg < R) {
                float4 rv = *(const float4*)&resid[(size_t)rg * DD + l * 4];
                o.x += rv.x; o.y += rv.y; o.z += rv.z; o.w += rv.w;
                *(float4*)&out[(size_t)rg * DD + l * 4] = o;
            }
        }
    }
}

extern "C" void kernel_launch(void* const* d_in, const int* in_sizes, int n_in,
                              void* d_out, int out_size)
{
    const float* efeat   = (const float*)d_in[0];
    const float* grid    = (const float*)d_in[1];
    const float* mesh    = (const float*)d_in[2];
    const int*   src_idx = (const int*)d_in[3];
    const int*   dst_idx = (const int*)d_in[4];
    const float* eW0 = (const float*)d_in[5];
    const float* eb0 = (const float*)d_in[6];
    const float* eW1 = (const float*)d_in[7];
    const float* eb1 = (const float*)d_in[8];
    const float* eg  = (const float*)d_in[9];
    const float* ebt = (const float*)d_in[10];
    const float* sW0 = (const float*)d_in[11];
    const float* sb0 = (const float*)d_in[12];
    const float* sW1 = (const float*)d_in[13];
    const float* sb1 = (const float*)d_in[14];
    const float* sg  = (const float*)d_in[15];
    const float* sbt = (const float*)d_in[16];
    const float* dW0 = (const float*)d_in[17];
    const float* db0 = (const float*)d_in[18];
    const float* dW1 = (const float*)d_in[19];
    const float* db1 = (const float*)d_in[20];
    const float* dg  = (const float*)d_in[21];
    const float* dbt = (const float*)d_in[22];

    float* out_grid = (float*)d_out;
    float* out_mesh = (float*)d_out + (size_t)NG * DD;

    float* agg_ptr = nullptr;
    cudaGetSymbolAddress((void**)&agg_ptr, g_agg);
    __half* wh_ptr = nullptr;
    cudaGetSymbolAddress((void**)&wh_ptr, g_wh);

    static bool attr_done = false;
    if (!attr_done) {
        cudaFuncSetAttribute(mlp_tc<384, 0>, cudaFuncAttributeMaxDynamicSharedMemorySize, SMEM_BYTES);
        cudaFuncSetAttribute(mlp_tc<128, 1>, cudaFuncAttributeMaxDynamicSharedMemorySize, SMEM_BYTES);
        cudaFuncSetAttribute(mlp_tc<256, 2>, cudaFuncAttributeMaxDynamicSharedMemorySize, SMEM_BYTES);
        attr_done = true;
    }

    prep_weights<<<576, 256>>>(eW0, eW1, sW0, sW1, dW0, dW1);
    zero_agg_kernel<<<512, 256>>>();

    const __half* weW0t = wh_ptr;
    const __half* weW1t = wh_ptr + 49152;
    const __half* wsW0t = wh_ptr + 65536;
    const __half* wsW1t = wh_ptr + 81920;
    const __half* wdW0t = wh_ptr + 98304;
    const __half* wdW1t = wh_ptr + 131072;

    mlp_tc<384, 0><<<NE / BLK_R, NTH, SMEM_BYTES>>>(
        efeat, grid, mesh, src_idx, dst_idx,
        weW0t, eb0, weW1t, eb1, eg, ebt,
        nullptr, nullptr, agg_ptr, NE);

    mlp_tc<128, 1><<<NG / BLK_R, NTH, SMEM_BYTES>>>(
        grid, nullptr, nullptr, nullptr, nullptr,
        wsW0t, sb0, wsW1t, sb1, sg, sbt,
        grid, out_grid, nullptr, NG);

    mlp_tc<256, 2><<<(NM + BLK_R - 1) / BLK_R, NTH, SMEM_BYTES>>>(
        agg_ptr, mesh, nullptr, nullptr, nullptr,
        wdW0t, db0, wdW1t, db1, dg, dbt,
        mesh, out_mesh, nullptr, NM);
}

// round 8
// speedup vs baseline: 7.1289x; 1.0598x over previous
#include <cuda_runtime.h>
#include <cuda_fp16.h>
#include <math.h>

#define NG 131072
#define NM 40962
#define NE 524288
#define DD 128

#define BLK_R 128
#define KC 32
#define NTH 256

#define AP 40     // A pitch (fp32 elems)
#define BPh 40    // B pitch (half elems) -> 80B rows, odd multiple of 16 => ldsm conflict-free
#define HPh 136   // H pitch (half elems) -> 272B rows
#define YP 132    // Y pitch (fp32 elems)

#define ASZ 20480            // 128*40*4 per A stage
#define BSZ 10240            // 128*40*2 per B stage
#define OFF_AS 0             // 3 A stages: 0..61440
#define OFF_BS 61440         // 3 B stages: 61440..92160
#define OFF_HS 0             // H fp16: 128*136*2 = 34816 (overlaps dead A)
#define OFF_Y  0             // Y fp32: 128*132*4 = 67584 (overlaps A + head of B0, all dead)
#define OFF_IS 92160
#define OFF_ID 92672
#define SMEM_BYTES 93184

__device__ float g_agg[(size_t)NM * DD];
// fp16 transposed weights: eW0t(128x384), eW1t, sW0t, sW1t, dW0t(128x256), dW1t
__device__ __half g_wh[147456];

__global__ void zero_agg_kernel() {
    size_t n = (size_t)NM * DD / 4;
    float4 z = make_float4(0.f, 0.f, 0.f, 0.f);
    float4* p = (float4*)g_agg;
    for (size_t i = blockIdx.x * (size_t)blockDim.x + threadIdx.x; i < n;
         i += (size_t)gridDim.x * blockDim.x) p[i] = z;
}

__global__ void prep_weights(const float* __restrict__ eW0, const float* __restrict__ eW1,
                             const float* __restrict__ sW0, const float* __restrict__ sW1,
                             const float* __restrict__ dW0, const float* __restrict__ dW1) {
    int i = blockIdx.x * blockDim.x + threadIdx.x;
    if (i >= 147456) return;
    float v;
    if (i < 49152)       { int j = i;          v = eW0[(j % 384) * 128 + (j / 384)]; }
    else if (i < 65536)  { int j = i - 49152;  v = eW1[(j % 128) * 128 + (j / 128)]; }
    else if (i < 81920)  { int j = i - 65536;  v = sW0[(j % 128) * 128 + (j / 128)]; }
    else if (i < 98304)  { int j = i - 81920;  v = sW1[(j % 128) * 128 + (j / 128)]; }
    else if (i < 131072) { int j = i - 98304;  v = dW0[(j % 256) * 128 + (j / 256)]; }
    else                 { int j = i - 131072; v = dW1[(j % 128) * 128 + (j / 128)]; }
    g_wh[i] = __float2half_rn(v);
}

__device__ __forceinline__ void cp16(unsigned saddr, const void* g, bool pred) {
    int sz = pred ? 16 : 0;
    asm volatile("cp.async.cg.shared.global [%0], [%1], 16, %2;\n"
                 :: "r"(saddr), "l"(g), "r"(sz));
}
#define CP_COMMIT asm volatile("cp.async.commit_group;\n")
template <int N>
__device__ __forceinline__ void cp_wait() {
    asm volatile("cp.async.wait_group %0;\n" :: "n"(N));
}

__device__ __forceinline__ unsigned packh2(float lo, float hi) {
    unsigned r;
    asm("cvt.rn.f16x2.f32 %0, %1, %2;" : "=r"(r) : "f"(hi), "f"(lo));
    return r;
}

__device__ __forceinline__ void ldsm4(unsigned& r0, unsigned& r1, unsigned& r2, unsigned& r3,
                                      unsigned addr) {
    asm volatile("ldmatrix.sync.aligned.m8n8.x4.shared.b16 {%0,%1,%2,%3}, [%4];"
                 : "=r"(r0), "=r"(r1), "=r"(r2), "=r"(r3) : "r"(addr));
}

__device__ __forceinline__ void mma16(float* d, const unsigned* a, unsigned b0, unsigned b1) {
    asm volatile(
        "mma.sync.aligned.m16n8k16.row.col.f32.f16.f16.f32 "
        "{%0,%1,%2,%3}, {%4,%5,%6,%7}, {%8,%9}, {%0,%1,%2,%3};\n"
        : "+f"(d[0]), "+f"(d[1]), "+f"(d[2]), "+f"(d[3])
        : "r"(a[0]), "r"(a[1]), "r"(a[2]), "r"(a[3]), "r"(b0), "r"(b1));
}

// MODE 0: edge MLP  (concat(efeat, grid[src], mesh[dst]) -> red.v4 scatter into agg[dst])
// MODE 1: plain MLP (Xa -> resid + out)
// MODE 2: dst MLP   (concat(agg, mesh) -> resid + out)
template <int K1, int MODE>
__global__ __launch_bounds__(NTH, 2)
void mlp_tc(const float* __restrict__ Xa,
            const float* __restrict__ Xb,
            const float* __restrict__ Xc,
            const int* __restrict__ src_idx,
            const int* __restrict__ dst_idx,
            const __half* __restrict__ W0t, const float* __restrict__ b0v,
            const __half* __restrict__ W1t, const float* __restrict__ b1v,
            const float* __restrict__ gamma, const float* __restrict__ beta,
            const float* __restrict__ resid,
            float* __restrict__ out,
            float* __restrict__ agg,
            int R)
{
    extern __shared__ unsigned char smem[];
    unsigned* Hu = (unsigned*)(smem + OFF_HS);
    float*    Ys = (float*)(smem + OFF_Y);
    int*      Is = (int*)(smem + OFF_IS);
    int*      Id = (int*)(smem + OFF_ID);
    const unsigned sbase = (unsigned)__cvta_generic_to_shared(smem);

    const int t   = threadIdx.x;
    const int wid = t >> 5;
    const int l   = t & 31;
    const int lr  = l >> 2;
    const int lc  = l & 3;
    const int warpM = wid >> 1;
    const int warpN = wid & 1;
    const int wr0 = warpM * 32;
    const int wc0 = warpN * 64;
    const int rowBase = blockIdx.x * BLK_R;

    // ldmatrix lane-address bases
    const int mi = l >> 3;       // matrix index within x4
    const int rr = l & 7;        // row within matrix
    // B fragment: group g loads matrices {(nt=2g,b0),(2g,b1),(2g+1,b0),(2g+1,b1)}
    const unsigned baseB = sbase + OFF_BS
        + 80u * (unsigned)(wc0 + 8 * (mi >> 1) + rr) + 16u * (unsigned)(mi & 1);
    // H fragment (GEMM2 A operand): matrices {(r-lo,k-lo),(r-hi,k-lo),(r-lo,k-hi),(r-hi,k-hi)}
    const unsigned baseH = sbase + OFF_HS
        + 272u * (unsigned)(wr0 + 8 * (mi & 1) + rr) + 16u * (unsigned)(mi >> 1);

    if (MODE == 0) {
        if (t < 128) {
            Is[t] = src_idx[rowBase + t];
            Id[t] = dst_idx[rowBase + t];
        }
        __syncthreads();
    }

    // ---- async tile loaders ----
    const int ac4 = (t & 7) * 4;
    const int arr = t >> 3;

    auto load_a = [&](int k0, int buf) {
#pragma unroll
        for (int j = 0; j < 4; ++j) {
            int r  = arr + j * 32;
            int rg = rowBase + r;
            bool pred = (MODE == 0) ? true : (rg < R);
            int rgc = pred ? rg : (R - 1);
            const float* src;
            if (MODE == 0) {
                int seg = k0 >> 7;
                int cc  = (k0 & 127) + ac4;
                src = (seg == 0) ? Xa + (size_t)rg * 128 + cc
                    : (seg == 1) ? Xb + (size_t)Is[r] * 128 + cc
                                 : Xc + (size_t)Id[r] * 128 + cc;
            } else if (MODE == 1) {
                src = Xa + (size_t)rgc * 128 + k0 + ac4;
            } else {
                int seg = k0 >> 7;
                int cc  = (k0 & 127) + ac4;
                src = (seg == 0) ? Xa + (size_t)rgc * 128 + cc
                                 : Xb + (size_t)rgc * 128 + cc;
            }
            cp16(sbase + OFF_AS + (unsigned)buf * ASZ + (unsigned)(r * AP + ac4) * 4u, src, pred);
        }
    };
    auto load_b = [&](const __half* Wt, int KS, int k0, int buf) {
#pragma unroll
        for (int j = 0; j < 2; ++j) {
            int idx = t + j * 256;
            int n = idx >> 2;
            int ch = idx & 3;
            cp16(sbase + OFF_BS + (unsigned)buf * BSZ + (unsigned)(n * BPh * 2 + ch * 16),
                 Wt + (size_t)n * KS + k0 + ch * 8, true);
        }
    };

    constexpr int NCH1 = K1 / KC;
    constexpr int NCH2 = 4;

    // ---------------- GEMM1: acc = f16(X) @ W0t ----------------
    float acc[2][8][4];
#pragma unroll
    for (int m = 0; m < 2; ++m)
#pragma unroll
        for (int n = 0; n < 8; ++n)
#pragma unroll
            for (int j = 0; j < 4; ++j) acc[m][n][j] = 0.0f;

    load_a(0, 0); load_b(W0t, K1, 0, 0); CP_COMMIT;
    load_a(KC, 1); load_b(W0t, K1, KC, 1); CP_COMMIT;

#pragma unroll 1
    for (int kb = 0; kb < NCH1; ++kb) {
        cp_wait<1>();
        __syncthreads();
        int p = kb + 2;
        if (p < NCH1) {
            load_a(p * KC, p % 3); load_b(W0t, K1, p * KC, p % 3); CP_COMMIT;
        } else if (p - NCH1 < NCH2) {
            load_b(W1t, 128, (p - NCH1) * KC, p % 3); CP_COMMIT;
        }
        const int bufc = kb % 3;
        const float* Af = (const float*)(smem + OFF_AS + bufc * ASZ);
        const unsigned bB = baseB + (unsigned)bufc * BSZ;
#pragma unroll
        for (int ks = 0; ks < 2; ++ks) {
            unsigned bfr[8][2];
#pragma unroll
            for (int g = 0; g < 4; ++g)
                ldsm4(bfr[2 * g][0], bfr[2 * g][1], bfr[2 * g + 1][0], bfr[2 * g + 1][1],
                      bB + 1280u * g + 32u * ks);
            unsigned a[2][4];
            int c0 = ks * 16 + 2 * lc;
#pragma unroll
            for (int mt = 0; mt < 2; ++mt) {
                int r = wr0 + mt * 16 + lr;
                float2 f0 = *(const float2*)&Af[r * AP + c0];
                float2 f1 = *(const float2*)&Af[(r + 8) * AP + c0];
                float2 f2 = *(const float2*)&Af[r * AP + c0 + 8];
                float2 f3 = *(const float2*)&Af[(r + 8) * AP + c0 + 8];
                a[mt][0] = packh2(f0.x, f0.y);
                a[mt][1] = packh2(f1.x, f1.y);
                a[mt][2] = packh2(f2.x, f2.y);
                a[mt][3] = packh2(f3.x, f3.y);
            }
#pragma unroll
            for (int nt = 0; nt < 8; ++nt) {
                mma16(acc[0][nt], a[0], bfr[nt][0], bfr[nt][1]);
                mma16(acc[1][nt], a[1], bfr[nt][0], bfr[nt][1]);
            }
        }
    }
    __syncthreads();   // all warps done with A stages before H overwrites them

    // bias + SiLU -> H (fp16, overlaps dead A region)
#pragma unroll
    for (int mt = 0; mt < 2; ++mt) {
#pragma unroll
        for (int nt = 0; nt < 8; ++nt) {
            int c  = wc0 + nt * 8 + 2 * lc;
            float2 bb = *(const float2*)&b0v[c];
            int r1 = wr0 + mt * 16 + lr;
            int r2 = r1 + 8;
            float x0 = acc[mt][nt][0] + bb.x;
            float x1 = acc[mt][nt][1] + bb.y;
            float x2 = acc[mt][nt][2] + bb.x;
            float x3 = acc[mt][nt][3] + bb.y;
            float s0 = x0 / (1.0f + __expf(-x0));
            float s1 = x1 / (1.0f + __expf(-x1));
            float s2 = x2 / (1.0f + __expf(-x2));
            float s3 = x3 / (1.0f + __expf(-x3));
            Hu[(r1 * HPh + c) >> 1] = packh2(s0, s1);
            Hu[(r2 * HPh + c) >> 1] = packh2(s2, s3);
        }
    }
    __syncthreads();

    // ---------------- GEMM2: y = H @ W1t ----------------
    float acc2[2][8][4];
#pragma unroll
    for (int m = 0; m < 2; ++m)
#pragma unroll
        for (int n = 0; n < 8; ++n)
#pragma unroll
            for (int j = 0; j < 4; ++j) acc2[m][n][j] = 0.0f;

#pragma unroll 1
    for (int j = 0; j < NCH2; ++j) {
        cp_wait<1>();
        __syncthreads();
        if (j + 2 < NCH2) { load_b(W1t, 128, (j + 2) * KC, (NCH1 + j + 2) % 3); CP_COMMIT; }
        const int bufc = (NCH1 + j) % 3;
        const unsigned bB = baseB + (unsigned)bufc * BSZ;
#pragma unroll
        for (int ks = 0; ks < 2; ++ks) {
            unsigned bfr[8][2];
#pragma unroll
            for (int g = 0; g < 4; ++g)
                ldsm4(bfr[2 * g][0], bfr[2 * g][1], bfr[2 * g + 1][0], bfr[2 * g + 1][1],
                      bB + 1280u * g + 32u * ks);
            unsigned a[2][4];
            unsigned hoff = 64u * j + 32u * ks;
#pragma unroll
            for (int mt = 0; mt < 2; ++mt)
                ldsm4(a[mt][0], a[mt][1], a[mt][2], a[mt][3],
                      baseH + 4352u * mt + hoff);
#pragma unroll
            for (int nt = 0; nt < 8; ++nt) {
                mma16(acc2[0][nt], a[0], bfr[nt][0], bfr[nt][1]);
                mma16(acc2[1][nt], a[1], bfr[nt][0], bfr[nt][1]);
            }
        }
    }
    __syncthreads();   // all compute done before Y overwrites A/B regions

    // y = acc2 + b1 -> Y (fp32)
#pragma unroll
    for (int mt = 0; mt < 2; ++mt) {
#pragma unroll
        for (int nt = 0; nt < 8; ++nt) {
            int c  = wc0 + nt * 8 + 2 * lc;
            float2 bb = *(const float2*)&b1v[c];
            int r1 = wr0 + mt * 16 + lr;
            int r2 = r1 + 8;
            float2 y1; y1.x = acc2[mt][nt][0] + bb.x; y1.y = acc2[mt][nt][1] + bb.y;
            float2 y2; y2.x = acc2[mt][nt][2] + bb.x; y2.y = acc2[mt][nt][3] + bb.y;
            *(float2*)&Ys[r1 * YP + c] = y1;
            *(float2*)&Ys[r2 * YP + c] = y2;
        }
    }
    __syncthreads();

    // ---------------- LayerNorm + epilogue ----------------
    float4 gg = *(const float4*)&gamma[l * 4];
    float4 bt = *(const float4*)&beta[l * 4];

#pragma unroll 1
    for (int i = 0; i < 16; ++i) {
        int r  = wid * 16 + i;
        int rg = rowBase + r;
        float4 v = *(const float4*)&Ys[r * YP + l * 4];
        float s  = v.x + v.y + v.z + v.w;
        float ss = v.x * v.x + v.y * v.y + v.z * v.z + v.w * v.w;
#pragma unroll
        for (int off = 16; off > 0; off >>= 1) {
            s  += __shfl_xor_sync(0xFFFFFFFFu, s,  off);
            ss += __shfl_xor_sync(0xFFFFFFFFu, ss, off);
        }
        float mean = s * (1.0f / DD);
        float var  = ss * (1.0f / DD) - mean * mean;
        float rstd = rsqrtf(var + 1e-5f);

        float4 o;
        o.x = (v.x - mean) * rstd * gg.x + bt.x;
        o.y = (v.y - mean) * rstd * gg.y + bt.y;
        o.z = (v.z - mean) * rstd * gg.z + bt.z;
        o.w = (v.w - mean) * rstd * gg.w + bt.w;

        if (MODE == 0) {
            float* p = &agg[(size_t)Id[r] * DD + l * 4];
            asm volatile("red.global.add.v4.f32 [%0], {%1,%2,%3,%4};"
                         :: "l"(p), "f"(o.x), "f"(o.y), "f"(o.z), "f"(o.w)
                         : "memory");
        } else {
            if (rg < R) {
                float4 rv = *(const float4*)&resid[(size_t)rg * DD + l * 4];
                o.x += rv.x; o.y += rv.y; o.z += rv.z; o.w += rv.w;
                *(float4*)&out[(size_t)rg * DD + l * 4] = o;
            }
        }
    }
}

extern "C" void kernel_launch(void* const* d_in, const int* in_sizes, int n_in,
                              void* d_out, int out_size)
{
    const float* efeat   = (const float*)d_in[0];
    const float* grid    = (const float*)d_in[1];
    const float* mesh    = (const float*)d_in[2];
    const int*   src_idx = (const int*)d_in[3];
    const int*   dst_idx = (const int*)d_in[4];
    const float* eW0 = (const float*)d_in[5];
    const float* eb0 = (const float*)d_in[6];
    const float* eW1 = (const float*)d_in[7];
    const float* eb1 = (const float*)d_in[8];
    const float* eg  = (const float*)d_in[9];
    const float* ebt = (const float*)d_in[10];
    const float* sW0 = (const float*)d_in[11];
    const float* sb0 = (const float*)d_in[12];
    const float* sW1 = (const float*)d_in[13];
    const float* sb1 = (const float*)d_in[14];
    const float* sg  = (const float*)d_in[15];
    const float* sbt = (const float*)d_in[16];
    const float* dW0 = (const float*)d_in[17];
    const float* db0 = (const float*)d_in[18];
    const float* dW1 = (const float*)d_in[19];
    const float* db1 = (const float*)d_in[20];
    const float* dg  = (const float*)d_in[21];
    const float* dbt = (const float*)d_in[22];

    float* out_grid = (float*)d_out;
    float* out_mesh = (float*)d_out + (size_t)NG * DD;

    float* agg_ptr = nullptr;
    cudaGetSymbolAddress((void**)&agg_ptr, g_agg);
    __half* wh_ptr = nullptr;
    cudaGetSymbolAddress((void**)&wh_ptr, g_wh);

    static bool attr_done = false;
    if (!attr_done) {
        cudaFuncSetAttribute(mlp_tc<384, 0>, cudaFuncAttributeMaxDynamicSharedMemorySize, SMEM_BYTES);
        cudaFuncSetAttribute(mlp_tc<128, 1>, cudaFuncAttributeMaxDynamicSharedMemorySize, SMEM_BYTES);
        cudaFuncSetAttribute(mlp_tc<256, 2>, cudaFuncAttributeMaxDynamicSharedMemorySize, SMEM_BYTES);
        attr_done = true;
    }

    prep_weights<<<576, 256>>>(eW0, eW1, sW0, sW1, dW0, dW1);
    zero_agg_kernel<<<512, 256>>>();

    const __half* weW0t = wh_ptr;
    const __half* weW1t = wh_ptr + 49152;
    const __half* wsW0t = wh_ptr + 65536;
    const __half* wsW1t = wh_ptr + 81920;
    const __half* wdW0t = wh_ptr + 98304;
    const __half* wdW1t = wh_ptr + 131072;

    mlp_tc<384, 0><<<NE / BLK_R, NTH, SMEM_BYTES>>>(
        efeat, grid, mesh, src_idx, dst_idx,
        weW0t, eb0, weW1t, eb1, eg, ebt,
        nullptr, nullptr, agg_ptr, NE);

    mlp_tc<128, 1><<<NG / BLK_R, NTH, SMEM_BYTES>>>(
        grid, nullptr, nullptr, nullptr, nullptr,
        wsW0t, sb0, wsW1t, sb1, sg, sbt,
        grid, out_grid, nullptr, NG);

    mlp_tc<256, 2><<<(NM + BLK_R - 1) / BLK_R, NTH, SMEM_BYTES>>>(
        agg_ptr, mesh, nullptr, nullptr, nullptr,
        wdW0t, db0, wdW1t, db1, dg, dbt,
        mesh, out_mesh, nullptr, NM);
}